// round 4
// baseline (speedup 1.0000x reference)
#include <cuda_runtime.h>

#define N_NODES 100000
#define N_EDGES 1000000
#define D 64
#define NEG_SLOPE 0.01f

// Scratch: aggregation buffer (25.6 MB). float4 type -> guaranteed 16B alignment
// for vector stores / red.global.add.v4.f32.
__device__ float4 g_agg4[N_NODES * D / 4];
__device__ int    g_idx_is64;   // 1 if edge_index buffer is int64, 0 if int32

// ---------------------------------------------------------------------------
// Kernel 0: detect edge-index dtype.
// View buffer as int32. For int64 data, odd words are high-words of values in
// [0,100000) -> all zero. For int32 data they are random node ids -> nonzero.
// Reads words [1..2047] -> in-bounds for both interpretations.
// ---------------------------------------------------------------------------
__global__ void detect_kernel(const int* __restrict__ ei32) {
    __shared__ int any_nonzero;
    if (threadIdx.x == 0) any_nonzero = 0;
    __syncthreads();
    int local = 0;
    for (int i = threadIdx.x; i < 1024; i += blockDim.x)
        local |= (ei32[2 * i + 1] != 0);
    if (local) atomicOr(&any_nonzero, 1);
    __syncthreads();
    if (threadIdx.x == 0) g_idx_is64 = (any_nonzero == 0) ? 1 : 0;
}

// ---------------------------------------------------------------------------
// Kernel 1: agg[i] = (1+eps) * x[i]   (float4 vectorized)
// ---------------------------------------------------------------------------
__global__ void init_kernel(const float4* __restrict__ x4,
                            const float* __restrict__ eps) {
    int i = blockIdx.x * blockDim.x + threadIdx.x;
    const int n4 = N_NODES * D / 4;
    if (i >= n4) return;
    float s = 1.0f + *eps;
    float4 v = x4[i];
    v.x *= s; v.y *= s; v.z *= s; v.w *= s;
    g_agg4[i] = v;
}

// ---------------------------------------------------------------------------
// Kernel 2: scatter-add  agg[dst] += x[src]
// 16 threads per edge, each one float4 chunk via red.global.add.v4.f32.
// All 16 lanes of a group load the same index words (L1 broadcast).
// ---------------------------------------------------------------------------
__global__ void scatter_kernel(const float4* __restrict__ x4,
                               const void* __restrict__ ei_raw) {
    int t = blockIdx.x * blockDim.x + threadIdx.x;
    int e = t >> 4;
    if (e >= N_EDGES) return;
    int c = t & 15;

    int src, dst;
    if (g_idx_is64) {
        const long long* ei = (const long long*)ei_raw;
        src = (int)__ldg(&ei[e]);
        dst = (int)__ldg(&ei[N_EDGES + e]);
    } else {
        const int* ei = (const int*)ei_raw;
        src = __ldg(&ei[e]);
        dst = __ldg(&ei[N_EDGES + e]);
    }
    // Defensive: wrong interpretation -> wrong answer, not a crash.
    if ((unsigned)src >= N_NODES || (unsigned)dst >= N_NODES) return;

    float4 v = __ldg(&x4[src * (D / 4) + c]);
    float4* p = &g_agg4[dst * (D / 4) + c];
    asm volatile("red.global.add.v4.f32 [%0], {%1,%2,%3,%4};"
                 :: "l"(p), "f"(v.x), "f"(v.y), "f"(v.z), "f"(v.w)
                 : "memory");
}

// ---------------------------------------------------------------------------
// Kernel 3: fused 2-layer MLP with LeakyReLU.
// Block = (64 cols, 8 rows) = 512 threads, 64 nodes per block, 8 nodes/thread.
// Smem: Ws (16KB, reloaded W1->W2) + h_s (16KB, reused in place) = 32.25 KB.
// ---------------------------------------------------------------------------
__global__ __launch_bounds__(512) void mlp_kernel(
    const float* __restrict__ W1, const float* __restrict__ b1,
    const float* __restrict__ W2, const float* __restrict__ b2,
    float* __restrict__ out) {
    __shared__ float Ws[D * D];
    __shared__ float bs[D];
    __shared__ float h_s[64][D];

    const int col = threadIdx.x;     // 0..63
    const int ty  = threadIdx.y;     // 0..7
    const int tid = ty * 64 + col;
    const int node0 = blockIdx.x * 64;
    const float* agg = (const float*)g_agg4;

    #pragma unroll
    for (int i = 0; i < 8; i++) {
        int r = ty + 8 * i;
        int n = node0 + r;
        h_s[r][col] = (n < N_NODES) ? agg[n * D + col] : 0.0f;
    }
    for (int i = tid; i < D * D; i += 512) Ws[i] = W1[i];
    if (tid < D) bs[tid] = b1[tid];
    __syncthreads();

    // ---- Layer 1 ----
    float acc[8];
    #pragma unroll
    for (int i = 0; i < 8; i++) acc[i] = bs[col];
    #pragma unroll
    for (int k = 0; k < D; k++) {
        float w = Ws[k * D + col];
        #pragma unroll
        for (int i = 0; i < 8; i++)
            acc[i] += h_s[ty + 8 * i][k] * w;
    }
    __syncthreads();   // all reads of h_s and Ws complete

    #pragma unroll
    for (int i = 0; i < 8; i++) {
        float a = acc[i];
        h_s[ty + 8 * i][col] = (a >= 0.0f) ? a : NEG_SLOPE * a;
    }
    for (int i = tid; i < D * D; i += 512) Ws[i] = W2[i];
    if (tid < D) bs[tid] = b2[tid];
    __syncthreads();

    // ---- Layer 2 ----
    #pragma unroll
    for (int i = 0; i < 8; i++) acc[i] = bs[col];
    #pragma unroll
    for (int k = 0; k < D; k++) {
        float w = Ws[k * D + col];
        #pragma unroll
        for (int i = 0; i < 8; i++)
            acc[i] += h_s[ty + 8 * i][k] * w;
    }
    #pragma unroll
    for (int i = 0; i < 8; i++) {
        int n = node0 + ty + 8 * i;
        if (n < N_NODES) {
            float a = acc[i];
            out[n * D + col] = (a >= 0.0f) ? a : NEG_SLOPE * a;
        }
    }
}

// ---------------------------------------------------------------------------
extern "C" void kernel_launch(void* const* d_in, const int* in_sizes, int n_in,
                              void* d_out, int out_size) {
    const float4* x4  = (const float4*)d_in[0];
    const void*   ei  = d_in[1];
    const float*  eps = (const float*)d_in[2];
    const float*  W1  = (const float*)d_in[3];
    const float*  b1  = (const float*)d_in[4];
    const float*  W2  = (const float*)d_in[5];
    const float*  b2  = (const float*)d_in[6];
    float*        out = (float*)d_out;

    // 0) detect int32 vs int64 edge indices
    detect_kernel<<<1, 256>>>((const int*)ei);

    // 1) agg = (1+eps) * x
    {
        int n4 = N_NODES * D / 4;
        init_kernel<<<(n4 + 255) / 256, 256>>>(x4, eps);
    }
    // 2) agg[dst] += x[src]  (16 threads/edge)
    {
        long long total = (long long)N_EDGES * 16;
        int blocks = (int)((total + 255) / 256);
        scatter_kernel<<<blocks, 256>>>(x4, ei);
    }
    // 3) out = leaky(leaky(agg @ W1 + b1) @ W2 + b2)
    {
        dim3 blk(64, 8);
        mlp_kernel<<<(N_NODES + 63) / 64, blk>>>(W1, b1, W2, b2, out);
    }
}

// round 6
// speedup vs baseline: 1.1852x; 1.1852x over previous
#include <cuda_runtime.h>

#define N_NODES 100000
#define N_EDGES 1000000
#define D 64
#define NEG_SLOPE 0.01f

// Scratch: aggregation buffer (25.6 MB). float4 type -> guaranteed 16B alignment.
__device__ float4 g_agg4[N_NODES * D / 4];
__device__ int    g_idx_is64;   // 1 if edge_index buffer is int64, 0 if int32

// ---------------------------------------------------------------------------
// Kernel 0: detect edge-index dtype (int64 -> odd 32-bit words all zero).
// ---------------------------------------------------------------------------
__global__ void detect_kernel(const int* __restrict__ ei32) {
    __shared__ int any_nonzero;
    if (threadIdx.x == 0) any_nonzero = 0;
    __syncthreads();
    int local = 0;
    for (int i = threadIdx.x; i < 1024; i += blockDim.x)
        local |= (ei32[2 * i + 1] != 0);
    if (local) atomicOr(&any_nonzero, 1);
    __syncthreads();
    if (threadIdx.x == 0) g_idx_is64 = (any_nonzero == 0) ? 1 : 0;
}

// ---------------------------------------------------------------------------
// Kernel 1: agg[i] = (1+eps) * x[i]   (float4 vectorized)
// ---------------------------------------------------------------------------
__global__ void init_kernel(const float4* __restrict__ x4,
                            const float* __restrict__ eps) {
    int i = blockIdx.x * blockDim.x + threadIdx.x;
    const int n4 = N_NODES * D / 4;
    if (i >= n4) return;
    float s = 1.0f + *eps;
    float4 v = x4[i];
    v.x *= s; v.y *= s; v.z *= s; v.w *= s;
    g_agg4[i] = v;
}

// ---------------------------------------------------------------------------
// Kernel 2: scatter-add  agg[dst] += x[src]
// 16 threads/edge, one float4 chunk each via red.global.add.v4.f32.
// ---------------------------------------------------------------------------
__global__ void scatter_kernel(const float4* __restrict__ x4,
                               const void* __restrict__ ei_raw) {
    int t = blockIdx.x * blockDim.x + threadIdx.x;
    int e = t >> 4;
    if (e >= N_EDGES) return;
    int c = t & 15;

    int src, dst;
    if (g_idx_is64) {
        const long long* ei = (const long long*)ei_raw;
        src = (int)__ldg(&ei[e]);
        dst = (int)__ldg(&ei[N_EDGES + e]);
    } else {
        const int* ei = (const int*)ei_raw;
        src = __ldg(&ei[e]);
        dst = __ldg(&ei[N_EDGES + e]);
    }
    if ((unsigned)src >= N_NODES || (unsigned)dst >= N_NODES) return;

    float4 v = __ldg(&x4[src * (D / 4) + c]);
    float4* p = &g_agg4[dst * (D / 4) + c];
    asm volatile("red.global.add.v4.f32 [%0], {%1,%2,%3,%4};"
                 :: "l"(p), "f"(v.x), "f"(v.y), "f"(v.z), "f"(v.w)
                 : "memory");
}

// ---------------------------------------------------------------------------
// Kernel 3: fused 2-layer MLP, 4x4 register tiling.
// Block (16,16) = 256 threads, tile = 64 nodes x 64 cols.
// Thread (tx,ty) computes rows 4*ty..+3, cols 4*tx..+3.
// k-loop unrolled by 4, all shared traffic via float4:
//   8 x LDS.128 per 64 FMAs  (was 9 scalar LDS per 8 FMAs).
// ---------------------------------------------------------------------------
__global__ __launch_bounds__(256) void mlp_kernel(
    const float4* __restrict__ W1, const float* __restrict__ b1,
    const float4* __restrict__ W2, const float* __restrict__ b2,
    float* __restrict__ out) {
    __shared__ float Ws[D * D];      // Ws[k][col], 16 KB
    __shared__ float bs[D];
    __shared__ float h_s[64][D];     // h_s[row][k], 16 KB, reused in place

    const int tx = threadIdx.x;      // 0..15 -> col group
    const int ty = threadIdx.y;      // 0..15 -> row group
    const int tid = ty * 16 + tx;    // 0..255
    const int node0 = blockIdx.x * 64;

    // ---- Stage h tile (float4 global loads, zero-pad tail rows) ----
    const float4 zero4 = make_float4(0.f, 0.f, 0.f, 0.f);
    #pragma unroll
    for (int i = 0; i < 4; i++) {
        int idx = tid + 256 * i;           // 0..1023 float4 slots
        int r  = idx >> 4;                 // row 0..63
        int c4 = idx & 15;                 // float4 col 0..15
        int n = node0 + r;
        float4 v = (n < N_NODES) ? g_agg4[n * 16 + c4] : zero4;
        *reinterpret_cast<float4*>(&h_s[r][c4 * 4]) = v;
    }
    // ---- Stage W1, b1 ----
    #pragma unroll
    for (int i = 0; i < 4; i++) {
        int idx = tid + 256 * i;           // 1024 float4 = 64x64
        reinterpret_cast<float4*>(Ws)[idx] = W1[idx];
    }
    if (tid < D) bs[tid] = b1[tid];
    __syncthreads();

    // ---- Layer 1: 4x4 register tile ----
    float acc[4][4];
    {
        float4 bv = *reinterpret_cast<const float4*>(&bs[4 * tx]);
        #pragma unroll
        for (int j = 0; j < 4; j++) {
            acc[j][0] = bv.x; acc[j][1] = bv.y; acc[j][2] = bv.z; acc[j][3] = bv.w;
        }
    }
    #pragma unroll
    for (int k0 = 0; k0 < D; k0 += 4) {
        float4 hv[4], wv[4];
        #pragma unroll
        for (int j = 0; j < 4; j++)
            hv[j] = *reinterpret_cast<const float4*>(&h_s[4 * ty + j][k0]);
        #pragma unroll
        for (int q = 0; q < 4; q++)
            wv[q] = *reinterpret_cast<const float4*>(&Ws[(k0 + q) * D + 4 * tx]);
        #pragma unroll
        for (int j = 0; j < 4; j++) {
            const float hk0 = hv[j].x, hk1 = hv[j].y, hk2 = hv[j].z, hk3 = hv[j].w;
            acc[j][0] += hk0 * wv[0].x + hk1 * wv[1].x + hk2 * wv[2].x + hk3 * wv[3].x;
            acc[j][1] += hk0 * wv[0].y + hk1 * wv[1].y + hk2 * wv[2].y + hk3 * wv[3].y;
            acc[j][2] += hk0 * wv[0].z + hk1 * wv[1].z + hk2 * wv[2].z + hk3 * wv[3].z;
            acc[j][3] += hk0 * wv[0].w + hk1 * wv[1].w + hk2 * wv[2].w + hk3 * wv[3].w;
        }
    }
    __syncthreads();   // all reads of h_s and Ws complete

    // ---- Activate + write back into h_s; stage W2, b2 ----
    #pragma unroll
    for (int j = 0; j < 4; j++) {
        float4 v;
        v.x = (acc[j][0] >= 0.f) ? acc[j][0] : NEG_SLOPE * acc[j][0];
        v.y = (acc[j][1] >= 0.f) ? acc[j][1] : NEG_SLOPE * acc[j][1];
        v.z = (acc[j][2] >= 0.f) ? acc[j][2] : NEG_SLOPE * acc[j][2];
        v.w = (acc[j][3] >= 0.f) ? acc[j][3] : NEG_SLOPE * acc[j][3];
        *reinterpret_cast<float4*>(&h_s[4 * ty + j][4 * tx]) = v;
    }
    #pragma unroll
    for (int i = 0; i < 4; i++) {
        int idx = tid + 256 * i;
        reinterpret_cast<float4*>(Ws)[idx] = W2[idx];
    }
    if (tid < D) bs[tid] = b2[tid];
    __syncthreads();

    // ---- Layer 2 ----
    {
        float4 bv = *reinterpret_cast<const float4*>(&bs[4 * tx]);
        #pragma unroll
        for (int j = 0; j < 4; j++) {
            acc[j][0] = bv.x; acc[j][1] = bv.y; acc[j][2] = bv.z; acc[j][3] = bv.w;
        }
    }
    #pragma unroll
    for (int k0 = 0; k0 < D; k0 += 4) {
        float4 hv[4], wv[4];
        #pragma unroll
        for (int j = 0; j < 4; j++)
            hv[j] = *reinterpret_cast<const float4*>(&h_s[4 * ty + j][k0]);
        #pragma unroll
        for (int q = 0; q < 4; q++)
            wv[q] = *reinterpret_cast<const float4*>(&Ws[(k0 + q) * D + 4 * tx]);
        #pragma unroll
        for (int j = 0; j < 4; j++) {
            const float hk0 = hv[j].x, hk1 = hv[j].y, hk2 = hv[j].z, hk3 = hv[j].w;
            acc[j][0] += hk0 * wv[0].x + hk1 * wv[1].x + hk2 * wv[2].x + hk3 * wv[3].x;
            acc[j][1] += hk0 * wv[0].y + hk1 * wv[1].y + hk2 * wv[2].y + hk3 * wv[3].y;
            acc[j][2] += hk0 * wv[0].z + hk1 * wv[1].z + hk2 * wv[2].z + hk3 * wv[3].z;
            acc[j][3] += hk0 * wv[0].w + hk1 * wv[1].w + hk2 * wv[2].w + hk3 * wv[3].w;
        }
    }

    // ---- Activate + store out (float4) ----
    #pragma unroll
    for (int j = 0; j < 4; j++) {
        int n = node0 + 4 * ty + j;
        if (n < N_NODES) {
            float4 v;
            v.x = (acc[j][0] >= 0.f) ? acc[j][0] : NEG_SLOPE * acc[j][0];
            v.y = (acc[j][1] >= 0.f) ? acc[j][1] : NEG_SLOPE * acc[j][1];
            v.z = (acc[j][2] >= 0.f) ? acc[j][2] : NEG_SLOPE * acc[j][2];
            v.w = (acc[j][3] >= 0.f) ? acc[j][3] : NEG_SLOPE * acc[j][3];
            *reinterpret_cast<float4*>(&out[n * D + 4 * tx]) = v;
        }
    }
}

// ---------------------------------------------------------------------------
extern "C" void kernel_launch(void* const* d_in, const int* in_sizes, int n_in,
                              void* d_out, int out_size) {
    const float4* x4  = (const float4*)d_in[0];
    const void*   ei  = d_in[1];
    const float*  eps = (const float*)d_in[2];
    const float4* W1  = (const float4*)d_in[3];
    const float*  b1  = (const float*)d_in[4];
    const float4* W2  = (const float4*)d_in[5];
    const float*  b2  = (const float*)d_in[6];
    float*        out = (float*)d_out;

    detect_kernel<<<1, 256>>>((const int*)ei);

    {
        int n4 = N_NODES * D / 4;
        init_kernel<<<(n4 + 255) / 256, 256>>>(x4, eps);
    }
    {
        long long total = (long long)N_EDGES * 16;
        int blocks = (int)((total + 255) / 256);
        scatter_kernel<<<blocks, 256>>>(x4, ei);
    }
    {
        dim3 blk(16, 16);
        mlp_kernel<<<(N_NODES + 63) / 64, blk>>>(W1, b1, W2, b2, out);
    }
}